// round 1
// baseline (speedup 1.0000x reference)
#include <cuda_runtime.h>

#define BATCH 8
#define DIM   64
#define TLEN  16384
#define INNER 128
#define TT    128
#define NTILES (TLEN/TT)

// Scratch (allowed: __device__ globals, allocated at module load)
__device__ float g_E[(size_t)BATCH*INNER*TLEN];   // 64 MB: exp(qraw)
__device__ float g_qsum[BATCH*INNER];
__device__ float g_ksum[BATCH*INNER];
__device__ float g_xsum[BATCH*DIM];
__device__ float g_A[BATCH*64*INNER];

__global__ void k_zero() {
    int i = blockIdx.x*blockDim.x + threadIdx.x;
    if (i < BATCH*INNER) { g_qsum[i] = 0.f; g_ksum[i] = 0.f; }
    if (i < BATCH*DIM)   { g_xsum[i] = 0.f; }
}

// 128(c) x 128(t) tile GEMM: acc[j][i] += ws[kk][ty*8+j] * xs[kk][tx*8+i]
__device__ __forceinline__ void mm_tile(const float* __restrict__ xs,
                                        const float* __restrict__ ws,
                                        int tx, int ty, float acc[8][8]) {
    #pragma unroll 4
    for (int kk = 0; kk < DIM; kk++) {
        float4 x0 = *(const float4*)&xs[kk*TT + tx*8];
        float4 x1 = *(const float4*)&xs[kk*TT + tx*8 + 4];
        float4 w0 = *(const float4*)&ws[kk*INNER + ty*8];
        float4 w1 = *(const float4*)&ws[kk*INNER + ty*8 + 4];
        float xv[8] = {x0.x,x0.y,x0.z,x0.w,x1.x,x1.y,x1.z,x1.w};
        float wv[8] = {w0.x,w0.y,w0.z,w0.w,w1.x,w1.y,w1.z,w1.w};
        #pragma unroll
        for (int j = 0; j < 8; j++)
            #pragma unroll
            for (int i = 0; i < 8; i++)
                acc[j][i] += wv[j] * xv[i];
    }
}

// Pass 1: per (b, t-tile): qraw -> exp -> E + qsum ; kraw -> per-t head softmax -> ksum ; xsum
__global__ void __launch_bounds__(256) k_reduce(const float* __restrict__ x,
                                                const float* __restrict__ wqkv) {
    extern __shared__ float sm[];
    float* xs  = sm;               // [64][TT]    32 KB
    float* ws  = sm + DIM*TT;      // [64][INNER] 32 KB (Wq then Wk, transposed)
    float* red = ws + DIM*INNER;   // [16][TT]     8 KB
    const int b   = blockIdx.y;
    const int t0  = blockIdx.x * TT;
    const int tid = threadIdx.x;
    const int tx  = tid & 15;   // t subtile (8 consecutive t each)
    const int ty  = tid >> 4;   // c subtile (8 consecutive c each)

    // load x tile (coalesced over t)
    const float* xb = x + (size_t)b*DIM*TLEN + t0;
    for (int idx = tid; idx < DIM*TT; idx += 256) {
        int kk = idx >> 7, t = idx & (TT-1);
        xs[idx] = xb[(size_t)kk*TLEN + t];
    }
    // load Wq transposed: ws[kk][c] = wqkv[c*64+kk]
    for (int idx = tid; idx < DIM*INNER; idx += 256) {
        int c = idx >> 6, kk = idx & 63;
        ws[kk*INNER + c] = wqkv[idx];
    }
    __syncthreads();

    // xsum (per-column sum of this tile)
    if (tid < DIM) {
        float s = 0.f;
        #pragma unroll 8
        for (int t = 0; t < TT; t++) s += xs[tid*TT + t];
        atomicAdd(&g_xsum[b*DIM + tid], s);
    }

    float acc[8][8];
    #pragma unroll
    for (int j = 0; j < 8; j++)
        #pragma unroll
        for (int i = 0; i < 8; i++) acc[j][i] = 0.f;

    // ---- Phase A: qraw ----
    mm_tile(xs, ws, tx, ty, acc);

    #pragma unroll
    for (int j = 0; j < 8; j++) {
        int c = ty*8 + j;
        float e[8]; float s = 0.f;
        #pragma unroll
        for (int i = 0; i < 8; i++) { e[i] = __expf(acc[j][i]); s += e[i]; }
        #pragma unroll
        for (int off = 8; off > 0; off >>= 1)
            s += __shfl_down_sync(0xffffffffu, s, off, 16);
        if (tx == 0) atomicAdd(&g_qsum[b*INNER + c], s);
        float4* ep = (float4*)&g_E[((size_t)b*INNER + c)*TLEN + t0 + tx*8];
        ep[0] = make_float4(e[0], e[1], e[2], e[3]);
        ep[1] = make_float4(e[4], e[5], e[6], e[7]);
    }
    __syncthreads();   // all Wq reads done

    // load Wk transposed
    for (int idx = tid; idx < DIM*INNER; idx += 256) {
        int c = idx >> 6, kk = idx & 63;
        ws[kk*INNER + c] = wqkv[INNER*DIM + idx];
    }
    __syncthreads();

    #pragma unroll
    for (int j = 0; j < 8; j++)
        #pragma unroll
        for (int i = 0; i < 8; i++) acc[j][i] = 0.f;

    // ---- Phase B: kraw ----
    mm_tile(xs, ws, tx, ty, acc);

    // exp + per-t partial sums over this thread's 8 channels
    float pt[8];
    #pragma unroll
    for (int i = 0; i < 8; i++) pt[i] = 0.f;
    #pragma unroll
    for (int j = 0; j < 8; j++)
        #pragma unroll
        for (int i = 0; i < 8; i++) {
            float e = __expf(acc[j][i]);
            acc[j][i] = e;
            pt[i] += e;
        }
    #pragma unroll
    for (int i = 0; i < 8; i++) red[ty*TT + tx*8 + i] = pt[i];
    __syncthreads();

    // head sums over d (32 channels = 4 consecutive ty rows), then ksum
    const int ty0 = ty & ~3;
    float inv[8];
    #pragma unroll
    for (int i = 0; i < 8; i++) {
        int t = tx*8 + i;
        float hs = red[ty0*TT + t] + red[(ty0+1)*TT + t]
                 + red[(ty0+2)*TT + t] + red[(ty0+3)*TT + t];
        inv[i] = __fdividef(1.f, hs);
    }
    #pragma unroll
    for (int j = 0; j < 8; j++) {
        float s = 0.f;
        #pragma unroll
        for (int i = 0; i < 8; i++) s += acc[j][i] * inv[i];
        #pragma unroll
        for (int off = 8; off > 0; off >>= 1)
            s += __shfl_down_sync(0xffffffffu, s, off, 16);
        if (tx == 0) atomicAdd(&g_ksum[b*INNER + ty*8 + j], s);
    }
}

// Pass 2 (tiny): vsum = Wv @ xsum ; A[b][o][c] = w_out[o][c] * ksum*vsum/qsum
__global__ void k_scale(const float* __restrict__ wqkv,
                        const float* __restrict__ wout) {
    int b = blockIdx.x, c = threadIdx.x;   // 128 threads
    __shared__ float ss[INNER];
    float vs = 0.f;
    const float* wv = wqkv + (size_t)(2*INNER + c)*DIM;
    #pragma unroll
    for (int kk = 0; kk < DIM; kk++) vs += wv[kk] * g_xsum[b*DIM + kk];
    ss[c] = g_ksum[b*INNER + c] * vs / g_qsum[b*INNER + c];
    __syncthreads();
    for (int idx = c; idx < 64*INNER; idx += 128) {
        int cc = idx & 127;
        g_A[b*64*INNER + idx] = wout[idx] * ss[cc];
    }
}

// Pass 3: y[b,o,t] = sum_c A[b,o,c] * E[b,c,t] + b_out[o]
__global__ void __launch_bounds__(256) k_out(const float* __restrict__ bout,
                                             float* __restrict__ y) {
    extern __shared__ float sm[];
    float* Es = sm;                  // [INNER][TT] 64 KB
    float* As = sm + INNER*TT;       // [INNER][64] 32 KB (transposed)
    float* bo = As + INNER*64;       // [64]
    const int b   = blockIdx.y;
    const int t0  = blockIdx.x * TT;
    const int tid = threadIdx.x;
    const int tx  = tid & 15;    // 8 t each
    const int ty  = tid >> 4;    // 4 o each

    for (int idx = tid; idx < INNER*TT; idx += 256)
        Es[idx] = g_E[((size_t)b*INNER + (idx >> 7))*TLEN + t0 + (idx & 127)];
    for (int idx = tid; idx < 64*INNER; idx += 256) {
        int o = idx >> 7, c = idx & 127;
        As[c*64 + o] = g_A[b*64*INNER + idx];
    }
    if (tid < 64) bo[tid] = bout[tid];
    __syncthreads();

    float acc[4][8];
    #pragma unroll
    for (int j = 0; j < 4; j++)
        #pragma unroll
        for (int i = 0; i < 8; i++) acc[j][i] = 0.f;

    #pragma unroll 4
    for (int c = 0; c < INNER; c++) {
        float4 e0 = *(const float4*)&Es[c*TT + tx*8];
        float4 e1 = *(const float4*)&Es[c*TT + tx*8 + 4];
        float4 av = *(const float4*)&As[c*64 + ty*4];
        float ev[8] = {e0.x,e0.y,e0.z,e0.w,e1.x,e1.y,e1.z,e1.w};
        float avv[4] = {av.x,av.y,av.z,av.w};
        #pragma unroll
        for (int j = 0; j < 4; j++)
            #pragma unroll
            for (int i = 0; i < 8; i++)
                acc[j][i] += avv[j] * ev[i];
    }

    #pragma unroll
    for (int j = 0; j < 4; j++) {
        int o = ty*4 + j;
        float bb = bo[o];
        float4 r0 = make_float4(acc[j][0]+bb, acc[j][1]+bb, acc[j][2]+bb, acc[j][3]+bb);
        float4 r1 = make_float4(acc[j][4]+bb, acc[j][5]+bb, acc[j][6]+bb, acc[j][7]+bb);
        float4* yp = (float4*)&y[((size_t)b*64 + o)*TLEN + t0 + tx*8];
        yp[0] = r0;
        yp[1] = r1;
    }
}

#define SMEM_REDUCE ((DIM*TT + DIM*INNER + 16*TT)*4)      /* 73728 */
#define SMEM_OUT    ((INNER*TT + INNER*64 + 64)*4)        /* 98560 */

extern "C" void kernel_launch(void* const* d_in, const int* in_sizes, int n_in,
                              void* d_out, int out_size) {
    const float* x    = (const float*)d_in[0];
    const float* wqkv = (const float*)d_in[1];
    const float* wout = (const float*)d_in[2];
    const float* bout = (const float*)d_in[3];
    float* y = (float*)d_out;

    cudaFuncSetAttribute((const void*)k_reduce,
                         cudaFuncAttributeMaxDynamicSharedMemorySize, SMEM_REDUCE);
    cudaFuncSetAttribute((const void*)k_out,
                         cudaFuncAttributeMaxDynamicSharedMemorySize, SMEM_OUT);

    k_zero<<<4, 256>>>();
    dim3 g(NTILES, BATCH);
    k_reduce<<<g, 256, SMEM_REDUCE>>>(x, wqkv);
    k_scale<<<BATCH, 128>>>(wqkv, wout);
    k_out<<<g, 256, SMEM_OUT>>>(bout, y);
}

// round 2
// speedup vs baseline: 1.0904x; 1.0904x over previous
#include <cuda_runtime.h>

typedef unsigned long long u64;

#define BATCH 8
#define DIM   64
#define TLEN  16384
#define INNER 128
#define TT    128
#define NTILES (TLEN/TT)
#define LOG2E 1.4426950408889634f

// Scratch (device globals; no runtime allocation)
__device__ float g_E[(size_t)BATCH*INNER*TLEN];   // 64 MB: exp(qraw)
__device__ float g_qsum[BATCH*INNER];
__device__ float g_ksum[BATCH*INNER];
__device__ float g_xsum[BATCH*DIM];
__device__ float g_A[BATCH*64*INNER];

// ---- packed fp32x2 helpers (Blackwell) ----
__device__ __forceinline__ u64 pack2(float lo, float hi) {
    u64 r; asm("mov.b64 %0, {%1,%2};" : "=l"(r) : "f"(lo), "f"(hi)); return r;
}
__device__ __forceinline__ u64 dup2(float v) { return pack2(v, v); }
__device__ __forceinline__ float2 unpack2(u64 v) {
    float lo, hi; asm("mov.b64 {%0,%1}, %2;" : "=f"(lo), "=f"(hi) : "l"(v));
    return make_float2(lo, hi);
}
__device__ __forceinline__ void fma2(u64 &d, u64 a, u64 b) {
    asm("fma.rn.f32x2 %0, %1, %2, %0;" : "+l"(d) : "l"(a), "l"(b));
}
__device__ __forceinline__ u64 add2(u64 a, u64 b) {
    u64 r; asm("add.rn.f32x2 %0, %1, %2;" : "=l"(r) : "l"(a), "l"(b)); return r;
}
__device__ __forceinline__ float ex2(float x) {
    float r; asm("ex2.approx.f32 %0, %1;" : "=f"(r) : "f"(x)); return r;
}
__device__ __forceinline__ float rcpa(float x) {
    float r; asm("rcp.approx.f32 %0, %1;" : "=f"(r) : "f"(x)); return r;
}

__global__ void k_zero() {
    int i = blockIdx.x*blockDim.x + threadIdx.x;
    if (i < BATCH*INNER) { g_qsum[i] = 0.f; g_ksum[i] = 0.f; }
    if (i < BATCH*DIM)   { g_xsum[i] = 0.f; }
}

// 128(c) x 128(t) tile GEMM with packed f32x2 over the t axis.
// acc[j][p] holds t-pair (tx*8+2p, tx*8+2p+1) for channel ty*8+j.
__device__ __forceinline__ void mm_tile2(const float* __restrict__ xs,
                                         const float* __restrict__ ws,
                                         int tx, int ty, u64 acc[8][4]) {
    #pragma unroll 4
    for (int kk = 0; kk < DIM; kk++) {
        ulonglong2 xa = *(const ulonglong2*)&xs[kk*TT + tx*8];
        ulonglong2 xb = *(const ulonglong2*)&xs[kk*TT + tx*8 + 4];
        float4 w0 = *(const float4*)&ws[kk*INNER + ty*8];
        float4 w1 = *(const float4*)&ws[kk*INNER + ty*8 + 4];
        float wv[8] = {w0.x,w0.y,w0.z,w0.w,w1.x,w1.y,w1.z,w1.w};
        #pragma unroll
        for (int j = 0; j < 8; j++) {
            u64 wd = dup2(wv[j]);
            fma2(acc[j][0], wd, xa.x);
            fma2(acc[j][1], wd, xa.y);
            fma2(acc[j][2], wd, xb.x);
            fma2(acc[j][3], wd, xb.y);
        }
    }
}

// Pass 1: per (b, t-tile): qraw -> exp2 -> E + qsum ; kraw -> per-t head softmax -> ksum ; xsum
__global__ void __launch_bounds__(256) k_reduce(const float* __restrict__ x,
                                                const float* __restrict__ wqkv) {
    extern __shared__ float sm[];
    float* xs  = sm;               // [64][TT]    32 KB
    float* ws  = sm + DIM*TT;      // [64][INNER] 32 KB (Wq then Wk, transposed, *log2e)
    float* red = ws + DIM*INNER;   // [16][TT]     8 KB
    const int b   = blockIdx.y;
    const int t0  = blockIdx.x * TT;
    const int tid = threadIdx.x;
    const int tx  = tid & 15;   // t subtile (8 consecutive t each)
    const int ty  = tid >> 4;   // c subtile (8 consecutive c each)

    const float* xb = x + (size_t)b*DIM*TLEN + t0;
    for (int idx = tid; idx < DIM*TT; idx += 256) {
        int kk = idx >> 7, t = idx & (TT-1);
        xs[idx] = xb[(size_t)kk*TLEN + t];
    }
    // Wq transposed, scaled by log2(e) so exp() == ex2()
    for (int idx = tid; idx < DIM*INNER; idx += 256) {
        int c = idx >> 6, kk = idx & 63;
        ws[kk*INNER + c] = wqkv[idx] * LOG2E;
    }
    __syncthreads();

    if (tid < DIM) {
        float s = 0.f;
        #pragma unroll 8
        for (int t = 0; t < TT; t++) s += xs[tid*TT + t];
        atomicAdd(&g_xsum[b*DIM + tid], s);
    }

    u64 acc[8][4];
    #pragma unroll
    for (int j = 0; j < 8; j++)
        #pragma unroll
        for (int p = 0; p < 4; p++) acc[j][p] = 0ull;

    // ---- Phase A: qraw ----
    mm_tile2(xs, ws, tx, ty, acc);

    #pragma unroll
    for (int j = 0; j < 8; j++) {
        int c = ty*8 + j;
        float e[8]; float s = 0.f;
        #pragma unroll
        for (int p = 0; p < 4; p++) {
            float2 v = unpack2(acc[j][p]);
            e[2*p]   = ex2(v.x);
            e[2*p+1] = ex2(v.y);
            s += e[2*p] + e[2*p+1];
        }
        #pragma unroll
        for (int off = 8; off > 0; off >>= 1)
            s += __shfl_down_sync(0xffffffffu, s, off, 16);
        if (tx == 0) atomicAdd(&g_qsum[b*INNER + c], s);
        ulonglong2 s0, s1;
        s0.x = pack2(e[0], e[1]); s0.y = pack2(e[2], e[3]);
        s1.x = pack2(e[4], e[5]); s1.y = pack2(e[6], e[7]);
        ulonglong2* ep = (ulonglong2*)&g_E[((size_t)b*INNER + c)*TLEN + t0 + tx*8];
        ep[0] = s0; ep[1] = s1;
    }
    __syncthreads();   // all Wq reads done

    // Wk transposed, *log2e
    for (int idx = tid; idx < DIM*INNER; idx += 256) {
        int c = idx >> 6, kk = idx & 63;
        ws[kk*INNER + c] = wqkv[INNER*DIM + idx] * LOG2E;
    }
    __syncthreads();

    #pragma unroll
    for (int j = 0; j < 8; j++)
        #pragma unroll
        for (int p = 0; p < 4; p++) acc[j][p] = 0ull;

    // ---- Phase B: kraw ----
    mm_tile2(xs, ws, tx, ty, acc);

    // exp2 + per-t partial sums (packed over t pairs)
    u64 pt2[4] = {0ull, 0ull, 0ull, 0ull};
    #pragma unroll
    for (int j = 0; j < 8; j++)
        #pragma unroll
        for (int p = 0; p < 4; p++) {
            float2 v = unpack2(acc[j][p]);
            u64 e2 = pack2(ex2(v.x), ex2(v.y));
            acc[j][p] = e2;
            pt2[p] = add2(pt2[p], e2);
        }
    #pragma unroll
    for (int p = 0; p < 4; p++)
        *(u64*)&red[ty*TT + tx*8 + 2*p] = pt2[p];
    __syncthreads();

    // head sums over d (32 channels = 4 consecutive ty rows) -> 1/hs, then ksum
    const int rbase = (ty & ~3)*TT + tx*8;
    u64 inv2[4];
    #pragma unroll
    for (int p = 0; p < 4; p++) {
        u64 h = add2(add2(*(const u64*)&red[rbase + 2*p],
                          *(const u64*)&red[rbase + TT + 2*p]),
                     add2(*(const u64*)&red[rbase + 2*TT + 2*p],
                          *(const u64*)&red[rbase + 3*TT + 2*p]));
        float2 hf = unpack2(h);
        inv2[p] = pack2(rcpa(hf.x), rcpa(hf.y));
    }
    #pragma unroll
    for (int j = 0; j < 8; j++) {
        u64 s2 = 0ull;
        #pragma unroll
        for (int p = 0; p < 4; p++) fma2(s2, acc[j][p], inv2[p]);
        float2 v = unpack2(s2);
        float s = v.x + v.y;
        #pragma unroll
        for (int off = 8; off > 0; off >>= 1)
            s += __shfl_down_sync(0xffffffffu, s, off, 16);
        if (tx == 0) atomicAdd(&g_ksum[b*INNER + ty*8 + j], s);
    }
}

// Pass 2 (tiny): vsum = Wv @ xsum ; A[b][o][c] = w_out[o][c] * ksum*vsum/qsum
__global__ void k_scale(const float* __restrict__ wqkv,
                        const float* __restrict__ wout) {
    int b = blockIdx.x, c = threadIdx.x;   // 128 threads
    __shared__ float ss[INNER];
    float vs = 0.f;
    const float* wv = wqkv + (size_t)(2*INNER + c)*DIM;
    #pragma unroll
    for (int kk = 0; kk < DIM; kk++) vs += wv[kk] * g_xsum[b*DIM + kk];
    ss[c] = g_ksum[b*INNER + c] * vs / g_qsum[b*INNER + c];
    __syncthreads();
    for (int idx = c; idx < 64*INNER; idx += 128) {
        int cc = idx & 127;
        g_A[b*64*INNER + idx] = wout[idx] * ss[cc];
    }
}

// Pass 3: y[b,o,t] = sum_c A[b,o,c] * E[b,c,t] + b_out[o]   (packed f32x2 over t)
__global__ void __launch_bounds__(256) k_out(const float* __restrict__ bout,
                                             float* __restrict__ y) {
    extern __shared__ float sm[];
    float* Es = sm;                  // [INNER][TT] 64 KB
    float* As = sm + INNER*TT;       // [INNER][64] 32 KB (transposed)
    float* bo = As + INNER*64;       // [64]
    const int b   = blockIdx.y;
    const int t0  = blockIdx.x * TT;
    const int tid = threadIdx.x;
    const int tx  = tid & 15;    // 8 t each
    const int ty  = tid >> 4;    // 4 o each

    for (int idx = tid; idx < INNER*TT; idx += 256)
        Es[idx] = g_E[((size_t)b*INNER + (idx >> 7))*TLEN + t0 + (idx & 127)];
    for (int idx = tid; idx < 64*INNER; idx += 256) {
        int o = idx >> 7, c = idx & 127;
        As[c*64 + o] = g_A[b*64*INNER + idx];
    }
    if (tid < 64) bo[tid] = bout[tid];
    __syncthreads();

    u64 acc[4][4];
    #pragma unroll
    for (int j = 0; j < 4; j++)
        #pragma unroll
        for (int p = 0; p < 4; p++) acc[j][p] = 0ull;

    #pragma unroll 4
    for (int c = 0; c < INNER; c++) {
        ulonglong2 ea = *(const ulonglong2*)&Es[c*TT + tx*8];
        ulonglong2 eb = *(const ulonglong2*)&Es[c*TT + tx*8 + 4];
        float4 av = *(const float4*)&As[c*64 + ty*4];
        float avv[4] = {av.x, av.y, av.z, av.w};
        #pragma unroll
        for (int j = 0; j < 4; j++) {
            u64 ad = dup2(avv[j]);
            fma2(acc[j][0], ad, ea.x);
            fma2(acc[j][1], ad, ea.y);
            fma2(acc[j][2], ad, eb.x);
            fma2(acc[j][3], ad, eb.y);
        }
    }

    #pragma unroll
    for (int j = 0; j < 4; j++) {
        int o = ty*4 + j;
        u64 bb = dup2(bo[o]);
        ulonglong2 r0, r1;
        r0.x = add2(acc[j][0], bb); r0.y = add2(acc[j][1], bb);
        r1.x = add2(acc[j][2], bb); r1.y = add2(acc[j][3], bb);
        ulonglong2* yp = (ulonglong2*)&y[((size_t)b*64 + o)*TLEN + t0 + tx*8];
        yp[0] = r0; yp[1] = r1;
    }
}

#define SMEM_REDUCE ((DIM*TT + DIM*INNER + 16*TT)*4)      /* 73728 */
#define SMEM_OUT    ((INNER*TT + INNER*64 + 64)*4)        /* 98560 */

extern "C" void kernel_launch(void* const* d_in, const int* in_sizes, int n_in,
                              void* d_out, int out_size) {
    const float* x    = (const float*)d_in[0];
    const float* wqkv = (const float*)d_in[1];
    const float* wout = (const float*)d_in[2];
    const float* bout = (const float*)d_in[3];
    float* y = (float*)d_out;

    cudaFuncSetAttribute((const void*)k_reduce,
                         cudaFuncAttributeMaxDynamicSharedMemorySize, SMEM_REDUCE);
    cudaFuncSetAttribute((const void*)k_out,
                         cudaFuncAttributeMaxDynamicSharedMemorySize, SMEM_OUT);

    k_zero<<<4, 256>>>();
    dim3 g(NTILES, BATCH);
    k_reduce<<<g, 256, SMEM_REDUCE>>>(x, wqkv);
    k_scale<<<BATCH, 128>>>(wqkv, wout);
    k_out<<<g, 256, SMEM_OUT>>>(bout, y);
}